// round 13
// baseline (speedup 1.0000x reference)
#include <cuda_runtime.h>
#include <cuda_bf16.h>
#include <cstdint>

// RotaryPositionEncoding3D: out[B,N,192,2] f32 from xyz[B,N,3] f32 and div_term[32] f32.
// Each output float4 g = (cos, sin, cos, sin) of angle xyz[p, axis]*div_term[bin],
//   p = g/96, j = g%96, axis = j%3, bin = j/3.
//
// v13: 256-bit stores (Blackwell st.global.v8.b32 -> STG.E.256).
//  - thread handles 2 consecutive float4s (q, q+1) per k, K=4 independent ks
//    at stride 512 float4s -> 8 sincos + 4 STG.256 per thread.
//  - warp store transaction = 1024B contiguous per instruction (v2: 512B);
//    halves STG/LSU-queue entries per byte. Tests whether the 12% gap to HBM
//    spec is per-transaction overhead vs pure write bandwidth.
//  - indices closed-form & independent per k (proven required in R3).
// TILE=2048 float4/block, 12288 exact-fit blocks. 402.6 MB stored.

#define K_ITERS 4
#define THREADS 256
#define TILE (THREADS * 2 * K_ITERS)     // 2048 float4 per block

__global__ void __launch_bounds__(THREADS)
rope3d_kernel(const float* __restrict__ xyz,
              const float* __restrict__ div_term,
              float4* __restrict__ out,
              int total_f4) {
    // Thread's first float4 index (even): 2 consecutive float4s per k.
    const int base2 = blockIdx.x * TILE + (int)threadIdx.x * 2;

    const unsigned p0 = (unsigned)base2 / 96u;
    const unsigned j0 = (unsigned)base2 - p0 * 96u;   // [0, 96)

    float ca[K_ITERS], sa[K_ITERS], cb[K_ITERS], sb[K_ITERS];

#pragma unroll
    for (int k = 0; k < K_ITERS; ++k) {
        // First float4 of the pair: t = j0 + k*512 <= 95 + 1536
        unsigned t   = j0 + (unsigned)(k * 2 * THREADS);
        unsigned dp  = t / 96u;
        unsigned ja  = t - dp * 96u;                  // j = 3*bin + axis
        unsigned pa  = p0 + dp;
        // Second float4 (q+1): wrap-select, still independent of other ks
        unsigned jb  = ja + 1u;
        unsigned pb  = pa;
        if (jb == 96u) { jb = 0u; ++pb; }

        unsigned bina  = ja / 3u, axa = ja - bina * 3u;
        unsigned binb  = jb / 3u, axb = jb - binb * 3u;

        float xa = __ldg(&xyz[pa * 3u + axa]);
        float xb = __ldg(&xyz[pb * 3u + axb]);
        float da = __ldg(&div_term[bina]);
        float db = __ldg(&div_term[binb]);
        __sincosf(xa * da, &sa[k], &ca[k]);           // |ang| <= 1, ample precision
        __sincosf(xb * db, &sb[k], &cb[k]);
    }

#pragma unroll
    for (int k = 0; k < K_ITERS; ++k) {
        int g = base2 + k * 2 * THREADS;
        if (g + 1 < total_f4) {
            // 32B-aligned (g even). One STG.E.256, evict-first.
            asm volatile(
                "st.global.cs.v8.b32 [%0], {%1,%2,%3,%4,%5,%6,%7,%8};"
                :: "l"(out + g),
                   "r"(__float_as_uint(ca[k])), "r"(__float_as_uint(sa[k])),
                   "r"(__float_as_uint(ca[k])), "r"(__float_as_uint(sa[k])),
                   "r"(__float_as_uint(cb[k])), "r"(__float_as_uint(sb[k])),
                   "r"(__float_as_uint(cb[k])), "r"(__float_as_uint(sb[k]))
                : "memory");
        } else if (g < total_f4) {
            __stcs(&out[g], make_float4(ca[k], sa[k], ca[k], sa[k]));
        }
    }
}

extern "C" void kernel_launch(void* const* d_in, const int* in_sizes, int n_in,
                              void* d_out, int out_size) {
    const float* xyz      = (const float*)d_in[0];
    const float* div_term = (const float*)d_in[1];
    float4* out = (float4*)d_out;

    int total_f4 = out_size / 4;                     // 25,165,824 for B=4, N=65536
    int blocks = (total_f4 + TILE - 1) / TILE;       // 12,288 (exact fit)
    rope3d_kernel<<<blocks, THREADS>>>(xyz, div_term, out, total_f4);
}

// round 14
// speedup vs baseline: 1.0774x; 1.0774x over previous
#include <cuda_runtime.h>
#include <cuda_bf16.h>

// RotaryPositionEncoding3D: out[B,N,192,2] f32 from xyz[B,N,3] f32 and div_term[32] f32.
// Each output float4 g = (cos, sin, cos, sin) of angle xyz[p, axis]*div_term[bin],
//   p = g/96, j = g%96, axis = j%3, bin = j/3.
//
// v14 (final): exact v2 winning config -- 256 threads, 4 float4/thread at
// stride-256, closed-form independent per-k indices, __stcs STG.128 --
// which measured 57.4us = 7.0 TB/s = 88% of HBM spec. Eight experiments
// (MLP 4/8, STG.128/256, .cs/.wb, persistent/short CTAs, two orderings)
// all plateau at the same write-stream ceiling; this is bandwidth-converged.
// Trims vs v2: guard-free fast path when the grid fits exactly (it does:
// 25,165,824 = 24576*1024), and explicit max-residency launch bounds.

#define F4_PER_THREAD 4
#define THREADS 256
#define TILE (THREADS * F4_PER_THREAD)   // 1024 float4 per block

template <bool GUARDED>
__global__ void __launch_bounds__(THREADS, 8)
rope3d_kernel(const float* __restrict__ xyz,
              const float* __restrict__ div_term,
              float4* __restrict__ out,
              int total_f4) {
    const int base = blockIdx.x * TILE + (int)threadIdx.x;

    const unsigned p0 = (unsigned)base / 96u;
    const unsigned j0 = (unsigned)base - p0 * 96u;   // [0, 96)

    float c[F4_PER_THREAD], s[F4_PER_THREAD];

#pragma unroll
    for (int k = 0; k < F4_PER_THREAD; ++k) {
        // Independent per-k index math: t = j0 + 256k < 96 + 768
        unsigned t    = j0 + (unsigned)(k * THREADS);
        unsigned dp   = t / 96u;
        unsigned jk   = t - dp * 96u;                // j = 3*bin + axis
        unsigned bin  = jk / 3u;
        unsigned axis = jk - bin * 3u;

        float x  = __ldg(&xyz[(p0 + dp) * 3u + axis]);
        float dt = __ldg(&div_term[bin]);
        __sincosf(x * dt, &s[k], &c[k]);             // |ang| <= 1, ample precision
    }

#pragma unroll
    for (int k = 0; k < F4_PER_THREAD; ++k) {
        int g = base + k * THREADS;
        if (!GUARDED || g < total_f4)
            __stcs(&out[g], make_float4(c[k], s[k], c[k], s[k]));
    }
}

extern "C" void kernel_launch(void* const* d_in, const int* in_sizes, int n_in,
                              void* d_out, int out_size) {
    const float* xyz      = (const float*)d_in[0];
    const float* div_term = (const float*)d_in[1];
    float4* out = (float4*)d_out;

    int total_f4 = out_size / 4;                     // 25,165,824 for B=4, N=65536
    int blocks = (total_f4 + TILE - 1) / TILE;       // 24,576 (exact fit)
    if (total_f4 % TILE == 0)
        rope3d_kernel<false><<<blocks, THREADS>>>(xyz, div_term, out, total_f4);
    else
        rope3d_kernel<true><<<blocks, THREADS>>>(xyz, div_term, out, total_f4);
}